// round 2
// baseline (speedup 1.0000x reference)
#include <cuda_runtime.h>

#define D   64
#define G3  192
#define NPAD 50176
#define EMAXSZ 800000

// ---------------- device scratch (no allocations allowed) ----------------
__device__ __align__(16) float g_h [NPAD * D];
__device__ __align__(16) float g_h2[NPAD * D];
__device__ __align__(16) float g_ah[NPAD * D];
__device__ __align__(16) float g_C [3 * D * G3];   // C_i = W_i @ W_ih^T
__device__ __align__(16) float g_W [D * G3];       // W_hh transposed [k][g]
__device__ int g_deg[NPAD];
__device__ int g_off[NPAD + 1];
__device__ int g_cur[NPAD];
__device__ int g_ssrc[EMAXSZ];

// ---------------- node transform: h = relu(x @ Wnt^T + bnt) ----------------
__global__ void k_nt(const float* __restrict__ x, const float* __restrict__ Wnt,
                     const float* __restrict__ bnt, int n) {
    int idx = blockIdx.x * blockDim.x + threadIdx.x;
    if (idx >= n * D) return;
    int node = idx >> 6, d = idx & 63;
    float acc = bnt[d];
    const float* xr = x + node * 6;
    const float* wr = Wnt + d * 6;
#pragma unroll
    for (int k = 0; k < 6; k++) acc = fmaf(xr[k], wr[k], acc);
    g_h[idx] = fmaxf(acc, 0.f);
}

// ---------------- precompute C_i[k][g] = sum_j weight[i][k][j] * W_ih[g][j] ----------------
__global__ void k_makeC(const float* __restrict__ wt, const float* __restrict__ Wih) {
    int idx = blockIdx.x * blockDim.x + threadIdx.x;
    if (idx >= 3 * D * G3) return;
    int g = idx % G3;
    int k = (idx / G3) & 63;
    int i = idx / (D * G3);
    const float* wr = wt + i * D * D + k * D;
    const float* ir = Wih + g * D;
    float s = 0.f;
#pragma unroll 8
    for (int j = 0; j < D; j++) s = fmaf(wr[j], ir[j], s);
    g_C[idx] = s;
}

// ---------------- transpose W_hh into [k][g] ----------------
__global__ void k_transW(const float* __restrict__ Whh) {
    int idx = blockIdx.x * blockDim.x + threadIdx.x;
    if (idx >= D * G3) return;
    int g = idx % G3, k = idx / G3;
    g_W[idx] = Whh[g * D + k];
}

// ---------------- CSR build: histogram / scan / scatter ----------------
__global__ void k_zero(int n) {
    int i = blockIdx.x * blockDim.x + threadIdx.x;
    if (i < n) g_deg[i] = 0;
}

// edge_index is int32 (JAX x64 disabled): src = ei[0..e), dst = ei[e..2e)
__global__ void k_hist(const int* __restrict__ ei, int e, int n) {
    int i = blockIdx.x * blockDim.x + threadIdx.x;
    if (i < e) {
        int d = ei[e + i];
        if ((unsigned)d < (unsigned)n) atomicAdd(&g_deg[d], 1);
    }
}

__global__ void k_scan(int n, int e) {
    __shared__ int part[1024];
    int t = threadIdx.x;
    int ch = (n + 1023) >> 10;
    int lo = t * ch, hi = lo + ch; if (hi > n) hi = n;
    int s = 0;
    for (int i = lo; i < hi; i++) s += g_deg[i];
    part[t] = s;
    __syncthreads();
    for (int ofs = 1; ofs < 1024; ofs <<= 1) {
        int v = (t >= ofs) ? part[t - ofs] : 0;
        __syncthreads();
        part[t] += v;
        __syncthreads();
    }
    int run = part[t] - s;               // exclusive prefix of this chunk
    for (int i = lo; i < hi; i++) {
        int d = g_deg[i];
        g_off[i] = run;
        g_cur[i] = run;
        run += d;
    }
    if (t == 0) g_off[n] = e;
}

__global__ void k_scatter(const int* __restrict__ ei, int e, int n) {
    int i = blockIdx.x * blockDim.x + threadIdx.x;
    if (i < e) {
        int dnode = ei[e + i];
        int snode = ei[i];
        if ((unsigned)dnode < (unsigned)n && (unsigned)snode < (unsigned)n) {
            int pos = atomicAdd(&g_cur[dnode], 1);
            g_ssrc[pos] = snode;
        }
    }
}

// ---------------- pull-based aggregate: ah[v] = sum_{e in CSR[v]} h[src[e]] ----------------
__global__ void k_agg(int hb, int n) {
    const float* __restrict__ hin = hb ? g_h2 : g_h;
    int w = (blockIdx.x * blockDim.x + threadIdx.x) >> 5;
    int lane = threadIdx.x & 31;
    if (w >= n) return;
    int beg = g_off[w], end = g_off[w + 1];
    const float2* h2 = (const float2*)hin;
    float ax = 0.f, ay = 0.f;
    for (int e0 = beg; e0 < end; e0 += 32) {
        int m = end - e0; if (m > 32) m = 32;
        int s = (lane < m) ? g_ssrc[e0 + lane] : 0;
#pragma unroll 4
        for (int j = 0; j < m; j++) {
            int sj = __shfl_sync(0xffffffffu, s, j);
            float2 v = __ldg(&h2[sj * 32 + lane]);
            ax += v.x; ay += v.y;
        }
    }
    float2 o; o.x = ax; o.y = ay;
    ((float2*)g_ah)[w * 32 + lane] = o;
}

// ---------------- fused GRU: gi = ah@C_i + b_ih ; gh = h@W_hh^T + b_hh ; gates ----------------
// Block: 256 threads, 32 nodes. Thread (c = tid&63, ng = tid>>6) owns
// gate-triplet columns {c, c+64, c+128} for 8 nodes -> 48 accumulators.
__global__ __launch_bounds__(256)
void k_gru(int hb, int layer, float* __restrict__ outp,
           const float* __restrict__ bi, const float* __restrict__ bh, int n) {
    const float* __restrict__ hin  = hb ? g_h2 : g_h;
    float* __restrict__ hout = outp ? outp : (hb ? g_h : g_h2);
    const float* __restrict__ Cmat = g_C + layer * D * G3;

    __shared__ float sC[16 * G3];   // 12 KB: 16-k chunk of C_i
    __shared__ float sW[16 * G3];   // 12 KB: 16-k chunk of W_hh^T
    __shared__ float sA[32 * D];    //  8 KB: ah tile
    __shared__ float sH[32 * D];    //  8 KB: h tile

    int tid = threadIdx.x;
    int node0 = blockIdx.x << 5;
    {
        const float4* A4 = (const float4*)(g_ah + node0 * D);
        const float4* H4 = (const float4*)(hin + node0 * D);
#pragma unroll
        for (int i = 0; i < 2; i++) {
            ((float4*)sA)[tid + (i << 8)] = A4[tid + (i << 8)];
            ((float4*)sH)[tid + (i << 8)] = H4[tid + (i << 8)];
        }
    }
    int c = tid & 63, ng = tid >> 6;
    float ai0[8], ai1[8], ai2[8], ah0[8], ah1[8], ah2[8];
#pragma unroll
    for (int j = 0; j < 8; j++) { ai0[j]=ai1[j]=ai2[j]=ah0[j]=ah1[j]=ah2[j]=0.f; }

    const float* Ab = sA + ng * 8 * D;
    const float* Hb = sH + ng * 8 * D;

    for (int kc = 0; kc < 4; kc++) {
        if (kc) __syncthreads();
        const float4* C4 = (const float4*)(Cmat + kc * 16 * G3);
        const float4* W4 = (const float4*)(g_W  + kc * 16 * G3);
#pragma unroll
        for (int i = 0; i < 3; i++) {
            ((float4*)sC)[tid + (i << 8)] = C4[tid + (i << 8)];
            ((float4*)sW)[tid + (i << 8)] = W4[tid + (i << 8)];
        }
        __syncthreads();
#pragma unroll 4
        for (int k2 = 0; k2 < 16; k2++) {
            int k = (kc << 4) + k2;
            float b0 = sC[k2 * G3 + c];
            float b1 = sC[k2 * G3 + 64 + c];
            float b2 = sC[k2 * G3 + 128 + c];
            float w0 = sW[k2 * G3 + c];
            float w1 = sW[k2 * G3 + 64 + c];
            float w2 = sW[k2 * G3 + 128 + c];
#pragma unroll
            for (int j = 0; j < 8; j++) {
                float av = Ab[j * D + k];
                float hv = Hb[j * D + k];
                ai0[j] = fmaf(av, b0, ai0[j]);
                ai1[j] = fmaf(av, b1, ai1[j]);
                ai2[j] = fmaf(av, b2, ai2[j]);
                ah0[j] = fmaf(hv, w0, ah0[j]);
                ah1[j] = fmaf(hv, w1, ah1[j]);
                ah2[j] = fmaf(hv, w2, ah2[j]);
            }
        }
    }

    float bi0 = bi[c], bi1 = bi[c + 64], bi2 = bi[c + 128];
    float bh0 = bh[c], bh1 = bh[c + 64], bh2 = bh[c + 128];
#pragma unroll
    for (int j = 0; j < 8; j++) {
        int node = node0 + ng * 8 + j;
        if (node < n) {
            float xr = ai0[j] + bi0 + ah0[j] + bh0;
            float xz = ai1[j] + bi1 + ah1[j] + bh1;
            float r = 1.f / (1.f + __expf(-xr));
            float z = 1.f / (1.f + __expf(-xz));
            float nn = tanhf(fmaf(r, ah2[j] + bh2, ai2[j] + bi2));
            float hp = sH[(ng * 8 + j) * D + c];
            hout[node * D + c] = (1.f - z) * nn + z * hp;
        }
    }
}

// ---------------- launch ----------------
extern "C" void kernel_launch(void* const* d_in, const int* in_sizes, int n_in,
                              void* d_out, int out_size) {
    const float* x   = (const float*)d_in[0];
    const int*   ei  = (const int*)d_in[1];      // int32: src[0..e), dst[e..2e)
    const float* Wnt = (const float*)d_in[4];
    const float* bnt = (const float*)d_in[5];
    const float* wt  = (const float*)d_in[6];
    const float* Wih = (const float*)d_in[7];
    const float* Whh = (const float*)d_in[8];
    const float* bi  = (const float*)d_in[9];
    const float* bh  = (const float*)d_in[10];
    float* out = (float*)d_out;

    int n = in_sizes[0] / 6;   // 50000
    int e = in_sizes[1] / 2;   // 800000

    // node transform + weight precompute + CSR build
    k_nt    <<<(n * D + 255) / 256, 256>>>(x, Wnt, bnt, n);
    k_makeC <<<(3 * D * G3 + 255) / 256, 256>>>(wt, Wih);
    k_transW<<<(D * G3 + 255) / 256, 256>>>(Whh);
    k_zero  <<<(n + 255) / 256, 256>>>(n);
    k_hist  <<<(e + 255) / 256, 256>>>(ei, e, n);
    k_scan  <<<1, 1024>>>(n, e);
    k_scatter<<<(e + 255) / 256, 256>>>(ei, e, n);

    int aggGrid = (n + 7) / 8;      // one warp per node
    int gruGrid = (n + 31) / 32;    // 32 nodes per block

    // layer 0: g_h -> g_h2
    k_agg<<<aggGrid, 256>>>(0, n);
    k_gru<<<gruGrid, 256>>>(0, 0, nullptr, bi, bh, n);
    // layer 1: g_h2 -> g_h
    k_agg<<<aggGrid, 256>>>(1, n);
    k_gru<<<gruGrid, 256>>>(1, 1, nullptr, bi, bh, n);
    // layer 2: g_h -> d_out
    k_agg<<<aggGrid, 256>>>(0, n);
    k_gru<<<gruGrid, 256>>>(0, 2, out, bi, bh, n);
}